// round 4
// baseline (speedup 1.0000x reference)
#include <cuda_runtime.h>

typedef unsigned long long u64;

__device__ __forceinline__ u64 pack2(float lo, float hi) {
    u64 r; asm("mov.b64 %0,{%1,%2};" : "=l"(r) : "f"(lo), "f"(hi)); return r;
}
__device__ __forceinline__ void unpack2(u64 v, float& lo, float& hi) {
    asm("mov.b64 {%0,%1}, %2;" : "=f"(lo), "=f"(hi) : "l"(v));
}
__device__ __forceinline__ u64 fma2(u64 a, u64 b, u64 c) {
    u64 d; asm("fma.rn.f32x2 %0,%1,%2,%3;" : "=l"(d) : "l"(a), "l"(b), "l"(c)); return d;
}
__device__ __forceinline__ u64 add2(u64 a, u64 b) {
    u64 d; asm("add.rn.f32x2 %0,%1,%2;" : "=l"(d) : "l"(a), "l"(b)); return d;
}
__device__ __forceinline__ u64 mul2(u64 a, u64 b) {
    u64 d; asm("mul.rn.f32x2 %0,%1,%2;" : "=l"(d) : "l"(a), "l"(b)); return d;
}

constexpr int NE = 7;      // entities
constexpr int DE = 4;      // dims per entity
constexpr int H  = 128;    // half embedding
constexpr int NPAIR = 21;  // unordered pairs
constexpr int OUTC = 2 * H;
constexpr int ROW = NE * OUTC;   // floats per batch element in out

__global__ __launch_bounds__(256)
void enc_kernel(const float* __restrict__ ctx,
                const float* __restrict__ w_prop, const float* __restrict__ b_prop,
                const float* __restrict__ w_rel,  const float* __restrict__ b_rel,
                float* __restrict__ out, int B, int G)
{
    // unordered pair list (i < j), compile-time so register indexing folds
    constexpr int PI[NPAIR] = {0,0,0,0,0,0,1,1,1,1,1,2,2,2,2,3,3,3,4,4,5};
    constexpr int PJ[NPAIR] = {1,2,3,4,5,6,2,3,4,5,6,3,4,5,6,4,5,6,5,6,6};

    // per slot: 2 batch elements packed as f32x2 {b, b+1}
    __shared__ __align__(16) u64 sh_ents [2][NE * DE];     // 28 u64 per slot
    __shared__ __align__(16) u64 sh_feats[2][NPAIR * 6];   // dx,dy,dz,dw,dist,pad

    const int tid  = threadIdx.x;
    const int slot = tid >> 7;       // 0..1
    const int h    = tid & (H - 1);  // 0..127

    // weights broadcast-packed once per thread (batch-invariant)
    u64 wp2[DE], wr2[DE + 1], bp2, br2;
    #pragma unroll
    for (int d = 0; d < DE; d++)     { float w = w_prop[d * H + h]; wp2[d] = pack2(w, w); }
    #pragma unroll
    for (int d = 0; d < DE + 1; d++) { float w = w_rel [d * H + h]; wr2[d] = pack2(w, w); }
    { float b = b_prop[h]; bp2 = pack2(b, b); }
    { float b = b_rel [h]; br2 = pack2(b, b); }

    for (int g = blockIdx.x; g < G; g += gridDim.x) {
        const int b0 = g * 4;  // block handles batches b0..b0+3 (2 per slot)

        __syncthreads();  // previous iteration's shared reads complete

        // ---- stage 1: coalesced load of 4 ctx columns into packed shared ----
        if (tid < 112) {
            const int r  = tid >> 2;   // 0..27  (entity*4 + dim)
            const int bb = tid & 3;    // 0..3
            float v = ctx[r * B + b0 + bb];
            ((float*)sh_ents[bb >> 1])[r * 2 + (bb & 1)] = v;
        }
        __syncthreads();

        // ---- stage 2: pair features (diffs + euclid dist over first 2 dims) ----
        if (tid < 84) {  // 2 slots * 2 batch-components * 21 pairs
            const int s    = tid / 42;
            const int rem  = tid - s * 42;
            const int comp = rem / 21;
            const int p    = rem - comp * 21;
            const int i = PI[p], j = PJ[p];
            const float* ef = (const float*)sh_ents[s];
            float dx = ef[(i*DE+0)*2+comp] - ef[(j*DE+0)*2+comp];
            float dy = ef[(i*DE+1)*2+comp] - ef[(j*DE+1)*2+comp];
            float dz = ef[(i*DE+2)*2+comp] - ef[(j*DE+2)*2+comp];
            float dw = ef[(i*DE+3)*2+comp] - ef[(j*DE+3)*2+comp];
            float dist = sqrtf(dx*dx + dy*dy);
            float* ff = (float*)sh_feats[s];
            ff[(p*6+0)*2+comp] = dx;
            ff[(p*6+1)*2+comp] = dy;
            ff[(p*6+2)*2+comp] = dz;
            ff[(p*6+3)*2+comp] = dw;
            ff[(p*6+4)*2+comp] = dist;
        }
        __syncthreads();

        // ---- stage 3: packed-f32x2 embedding compute, one h per thread ----
        const int bA = b0 + slot * 2;
        float* out0 = out + (size_t)bA * ROW;
        float* out1 = out0 + ROW;   // batch bA+1

        // property embedding: relu(ents @ w_prop + b_prop)
        const ulonglong2* e4 = (const ulonglong2*)sh_ents[slot];
        #pragma unroll
        for (int e = 0; e < NE; e++) {
            ulonglong2 q0 = e4[e*2 + 0];  // d0, d1 (each packed over 2 batches)
            ulonglong2 q1 = e4[e*2 + 1];  // d2, d3
            u64 acc = fma2(q0.x, wp2[0], bp2);
            acc = fma2(q0.y, wp2[1], acc);
            acc = fma2(q1.x, wp2[2], acc);
            acc = fma2(q1.y, wp2[3], acc);
            float lo, hi; unpack2(acc, lo, hi);
            out0[e * OUTC + h] = fmaxf(lo, 0.f);
            out1[e * OUTC + h] = fmaxf(hi, 0.f);
        }

        // relation embedding: sum_{j != i} relu(feats(i,j) @ w_rel + b_rel)
        float rlo[NE], rhi[NE];
        #pragma unroll
        for (int e = 0; e < NE; e++) { rlo[e] = 0.f; rhi[e] = 0.f; }

        const u64* fbase = sh_feats[slot];
        #pragma unroll
        for (int p = 0; p < NPAIR; p++) {
            const ulonglong2* fp = (const ulonglong2*)(fbase + p * 6);
            ulonglong2 q0 = fp[0];            // dx, dy
            ulonglong2 q1 = fp[1];            // dz, dw
            u64 dist2 = fbase[p * 6 + 4];
            // s_diff = diff . w_rel[0:4]   (antisymmetric part)
            u64 sd = mul2(q1.y, wr2[3]);
            sd = fma2(q1.x, wr2[2], sd);
            sd = fma2(q0.y, wr2[1], sd);
            sd = fma2(q0.x, wr2[0], sd);
            // s_base = dist * w_rel[4] + b_rel   (symmetric part)
            u64 sb  = fma2(dist2, wr2[4], br2);
            u64 rij = add2(sb, sd);
            u64 rji = add2(sb, sd ^ 0x8000000080000000ULL);  // negate both lanes
            float ij_lo, ij_hi, ji_lo, ji_hi;
            unpack2(rij, ij_lo, ij_hi);
            unpack2(rji, ji_lo, ji_hi);
            const int i = PI[p], j = PJ[p];
            rlo[i] += fmaxf(ij_lo, 0.f); rhi[i] += fmaxf(ij_hi, 0.f);
            rlo[j] += fmaxf(ji_lo, 0.f); rhi[j] += fmaxf(ji_hi, 0.f);
        }

        #pragma unroll
        for (int e = 0; e < NE; e++) {
            out0[e * OUTC + H + h] = rlo[e];
            out1[e * OUTC + H + h] = rhi[e];
        }
    }
}

extern "C" void kernel_launch(void* const* d_in, const int* in_sizes, int n_in,
                              void* d_out, int out_size) {
    const float* ctx    = (const float*)d_in[0];
    const float* w_prop = (const float*)d_in[1];
    const float* b_prop = (const float*)d_in[2];
    const float* w_rel  = (const float*)d_in[3];
    const float* b_rel  = (const float*)d_in[4];
    float* out = (float*)d_out;

    const int B = in_sizes[0] / (NE * DE);   // 16384
    const int G = B / 4;                     // 4 batches per block-group
    int grid = G < 2048 ? G : 2048;
    enc_kernel<<<grid, 256>>>(ctx, w_prop, b_prop, w_rel, b_rel, out, B, G);
}

// round 6
// speedup vs baseline: 1.1691x; 1.1691x over previous
#include <cuda_runtime.h>

typedef unsigned long long u64;

__device__ __forceinline__ u64 pack2(float lo, float hi) {
    u64 r; asm("mov.b64 %0,{%1,%2};" : "=l"(r) : "f"(lo), "f"(hi)); return r;
}
__device__ __forceinline__ void unpack2(u64 v, float& lo, float& hi) {
    asm("mov.b64 {%0,%1}, %2;" : "=f"(lo), "=f"(hi) : "l"(v));
}
__device__ __forceinline__ u64 fma2(u64 a, u64 b, u64 c) {
    u64 d; asm("fma.rn.f32x2 %0,%1,%2,%3;" : "=l"(d) : "l"(a), "l"(b), "l"(c)); return d;
}
__device__ __forceinline__ u64 add2(u64 a, u64 b) {
    u64 d; asm("add.rn.f32x2 %0,%1,%2;" : "=l"(d) : "l"(a), "l"(b)); return d;
}
__device__ __forceinline__ u64 mul2(u64 a, u64 b) {
    u64 d; asm("mul.rn.f32x2 %0,%1,%2;" : "=l"(d) : "l"(a), "l"(b)); return d;
}
__device__ __forceinline__ float sqrt_approx(float x) {
    float r; asm("sqrt.approx.f32 %0, %1;" : "=f"(r) : "f"(x)); return r;
}
// relu both halves of a packed f32x2 (repack is register-renaming, free)
__device__ __forceinline__ u64 relu2(u64 v) {
    float lo, hi; unpack2(v, lo, hi);
    return pack2(fmaxf(lo, 0.f), fmaxf(hi, 0.f));
}

constexpr int NE = 7;      // entities
constexpr int DE = 4;      // dims per entity
constexpr int H  = 128;    // half embedding
constexpr int NPAIR = 21;  // unordered pairs
constexpr int OUTC = 2 * H;
constexpr int ROW = NE * OUTC;   // floats per batch element in out

__global__ __launch_bounds__(256, 4)
void enc_kernel(const float* __restrict__ ctx,
                const float* __restrict__ w_prop, const float* __restrict__ b_prop,
                const float* __restrict__ w_rel,  const float* __restrict__ b_rel,
                float* __restrict__ out, int B)
{
    constexpr int PI[NPAIR] = {0,0,0,0,0,0,1,1,1,1,1,2,2,2,2,3,3,3,4,4,5};
    constexpr int PJ[NPAIR] = {1,2,3,4,5,6,2,3,4,5,6,3,4,5,6,4,5,6,5,6,6};

    // two independent 128-thread sub-blocks per CTA, each owns 2 batches
    __shared__ __align__(16) u64 sh_ents [2][NE * DE];
    __shared__ __align__(16) u64 sh_feats[2][NPAIR * 6];

    const int tid = threadIdx.x;
    const int s   = tid >> 7;        // sub-block 0/1
    const int t   = tid & 127;       // lane within sub-block
    const int h   = t;               // one output column per thread

    // batch pair owned by this sub-block
    const int b0 = blockIdx.x * 4 + s * 2;

    // ---- stage 1: LDG.64 of {b0, b0+1} is exactly the packed layout ----
    if (t < NE * DE) {
        const float2 v = *(const float2*)(ctx + t * B + b0);
        sh_ents[s][t] = pack2(v.x, v.y);
    }

    // weights broadcast-packed (batch-invariant) — overlaps with stage-1 latency
    u64 wp2[DE], wr2[DE + 1], bp2, br2;
    #pragma unroll
    for (int d = 0; d < DE; d++)     { float w = w_prop[d * H + h]; wp2[d] = pack2(w, w); }
    #pragma unroll
    for (int d = 0; d < DE + 1; d++) { float w = w_rel [d * H + h]; wr2[d] = pack2(w, w); }
    { float b = b_prop[h]; bp2 = pack2(b, b); }
    { float b = b_rel [h]; br2 = pack2(b, b); }

    asm volatile("bar.sync %0, 128;" :: "r"(s + 1) : "memory");

    // ---- stage 2: pair features (diffs + euclid dist over first 2 coords) ----
    if (t < 2 * NPAIR) {
        const int comp = t >= NPAIR;         // batch component (lo/hi)
        const int p    = comp ? t - NPAIR : t;
        const int i = PI[p], j = PJ[p];
        const float* ef = (const float*)sh_ents[s];
        float dx = ef[(i*DE+0)*2+comp] - ef[(j*DE+0)*2+comp];
        float dy = ef[(i*DE+1)*2+comp] - ef[(j*DE+1)*2+comp];
        float dz = ef[(i*DE+2)*2+comp] - ef[(j*DE+2)*2+comp];
        float dw = ef[(i*DE+3)*2+comp] - ef[(j*DE+3)*2+comp];
        float dist = sqrt_approx(dx*dx + dy*dy);
        float* ff = (float*)sh_feats[s];
        ff[(p*6+0)*2+comp] = dx;
        ff[(p*6+1)*2+comp] = dy;
        ff[(p*6+2)*2+comp] = dz;
        ff[(p*6+3)*2+comp] = dw;
        ff[(p*6+4)*2+comp] = dist;
    }
    asm volatile("bar.sync %0, 128;" :: "r"(s + 1) : "memory");

    // ---- stage 3: packed-f32x2 compute, one h per thread ----
    float* out0 = out + (size_t)b0 * ROW;
    float* out1 = out0 + ROW;     // batch b0+1

    // property embedding: relu(ents @ w_prop + b_prop)
    const ulonglong2* e4 = (const ulonglong2*)sh_ents[s];
    #pragma unroll
    for (int e = 0; e < NE; e++) {
        ulonglong2 q0 = e4[e*2 + 0];   // d0, d1 (each packed over 2 batches)
        ulonglong2 q1 = e4[e*2 + 1];   // d2, d3
        u64 acc = fma2(q0.x, wp2[0], bp2);
        acc = fma2(q0.y, wp2[1], acc);
        acc = fma2(q1.x, wp2[2], acc);
        acc = fma2(q1.y, wp2[3], acc);
        float lo, hi; unpack2(acc, lo, hi);
        out0[e * OUTC + h] = fmaxf(lo, 0.f);
        out1[e * OUTC + h] = fmaxf(hi, 0.f);
    }

    // relation embedding: sum_{j != i} relu(feats(i,j) @ w_rel + b_rel)
    u64 racc[NE];
    #pragma unroll
    for (int e = 0; e < NE; e++) racc[e] = 0ULL;

    const u64* fbase = sh_feats[s];
    #pragma unroll
    for (int p = 0; p < NPAIR; p++) {
        const ulonglong2* fp = (const ulonglong2*)(fbase + p * 6);
        ulonglong2 q0 = fp[0];             // dx, dy
        ulonglong2 q1 = fp[1];             // dz, dw
        u64 dist2 = fbase[p * 6 + 4];
        // antisymmetric part: diff . w_rel[0:4]
        u64 sd = mul2(q1.y, wr2[3]);
        sd = fma2(q1.x, wr2[2], sd);
        sd = fma2(q0.y, wr2[1], sd);
        sd = fma2(q0.x, wr2[0], sd);
        // symmetric part: dist * w_rel[4] + b_rel
        u64 sb  = fma2(dist2, wr2[4], br2);
        const int i = PI[p], j = PJ[p];
        racc[i] = add2(racc[i], relu2(add2(sb, sd)));
        racc[j] = add2(racc[j], relu2(add2(sb, sd ^ 0x8000000080000000ULL)));
    }

    #pragma unroll
    for (int e = 0; e < NE; e++) {
        float lo, hi; unpack2(racc[e], lo, hi);
        out0[e * OUTC + H + h] = lo;
        out1[e * OUTC + H + h] = hi;
    }
}

extern "C" void kernel_launch(void* const* d_in, const int* in_sizes, int n_in,
                              void* d_out, int out_size) {
    const float* ctx    = (const float*)d_in[0];
    const float* w_prop = (const float*)d_in[1];
    const float* b_prop = (const float*)d_in[2];
    const float* w_rel  = (const float*)d_in[3];
    const float* b_rel  = (const float*)d_in[4];
    float* out = (float*)d_out;

    const int B = in_sizes[0] / (NE * DE);   // 16384
    enc_kernel<<<B / 4, 256>>>(ctx, w_prop, b_prop, w_rel, b_rel, out, B);
}

// round 7
// speedup vs baseline: 1.4040x; 1.2009x over previous
#include <cuda_runtime.h>

typedef unsigned long long u64;

__device__ __forceinline__ u64 pack2(float lo, float hi) {
    u64 r; asm("mov.b64 %0,{%1,%2};" : "=l"(r) : "f"(lo), "f"(hi)); return r;
}
__device__ __forceinline__ void unpack2(u64 v, float& lo, float& hi) {
    asm("mov.b64 {%0,%1}, %2;" : "=f"(lo), "=f"(hi) : "l"(v));
}
__device__ __forceinline__ u64 fma2(u64 a, u64 b, u64 c) {
    u64 d; asm("fma.rn.f32x2 %0,%1,%2,%3;" : "=l"(d) : "l"(a), "l"(b), "l"(c)); return d;
}
__device__ __forceinline__ u64 add2(u64 a, u64 b) {
    u64 d; asm("add.rn.f32x2 %0,%1,%2;" : "=l"(d) : "l"(a), "l"(b)); return d;
}
__device__ __forceinline__ u64 mul2(u64 a, u64 b) {
    u64 d; asm("mul.rn.f32x2 %0,%1,%2;" : "=l"(d) : "l"(a), "l"(b)); return d;
}
__device__ __forceinline__ float sqrt_approx(float x) {
    float r; asm("sqrt.approx.f32 %0, %1;" : "=f"(r) : "f"(x)); return r;
}
// relu both halves of a packed f32x2 (repack is register renaming, ~2 FMNMX)
__device__ __forceinline__ u64 relu2(u64 v) {
    float lo, hi; unpack2(v, lo, hi);
    return pack2(fmaxf(lo, 0.f), fmaxf(hi, 0.f));
}

constexpr int NE = 7;      // entities
constexpr int DE = 4;      // dims per entity
constexpr int H  = 128;    // half embedding
constexpr int NPAIR = 21;  // unordered pairs
constexpr int OUTC = 2 * H;
constexpr int ROW = NE * OUTC;   // floats per batch element in out

__global__ __launch_bounds__(256, 4)
void enc_kernel(const float* __restrict__ ctx,
                const float* __restrict__ w_prop, const float* __restrict__ b_prop,
                const float* __restrict__ w_rel,  const float* __restrict__ b_rel,
                float* __restrict__ out, int B)
{
    constexpr int PI[NPAIR] = {0,0,0,0,0,0,1,1,1,1,1,2,2,2,2,3,3,3,4,4,5};
    constexpr int PJ[NPAIR] = {1,2,3,4,5,6,2,3,4,5,6,3,4,5,6,4,5,6,5,6,6};

    // two independent 128-thread sub-blocks per CTA, each owns 2 batches
    __shared__ __align__(16) u64 sh_ents[2][NE * DE];   // packed {b0, b0+1}
    __shared__ __align__(16) u64 sh_dist[2][NPAIR];     // packed pair distances

    const int tid = threadIdx.x;
    const int s   = tid >> 7;        // sub-block 0/1
    const int t   = tid & 127;       // lane within sub-block
    const int h   = t;               // one output column per thread

    const int b0 = blockIdx.x * 4 + s * 2;   // batch pair owned by sub-block

    // ---- stage 1: LDG.64 of {b0, b0+1} is exactly the packed layout ----
    if (t < NE * DE) {
        const float2 v = *(const float2*)(ctx + t * B + b0);
        sh_ents[s][t] = pack2(v.x, v.y);
    }

    // weights broadcast-packed (batch-invariant) — overlaps with stage-1 latency
    u64 wp2[DE], wr2[DE + 1], bp2, br2;
    #pragma unroll
    for (int d = 0; d < DE; d++)     { float w = w_prop[d * H + h]; wp2[d] = pack2(w, w); }
    #pragma unroll
    for (int d = 0; d < DE + 1; d++) { float w = w_rel [d * H + h]; wr2[d] = pack2(w, w); }
    { float b = b_prop[h]; bp2 = pack2(b, b); }
    { float b = b_rel [h]; br2 = pack2(b, b); }
    const u64 neg1 = pack2(-1.f, -1.f);

    asm volatile("bar.sync %0, 128;" :: "r"(s + 1) : "memory");

    // ---- stage 2: pair distances over first 2 coords only ----
    if (t < 2 * NPAIR) {
        const int comp = t >= NPAIR;          // batch component (lo/hi)
        const int p    = comp ? t - NPAIR : t;
        const int i = PI[p], j = PJ[p];
        const float* ef = (const float*)sh_ents[s];
        float dx = ef[(i*DE+0)*2+comp] - ef[(j*DE+0)*2+comp];
        float dy = ef[(i*DE+1)*2+comp] - ef[(j*DE+1)*2+comp];
        ((float*)sh_dist[s])[p * 2 + comp] = sqrt_approx(dx*dx + dy*dy);
    }
    asm volatile("bar.sync %0, 128;" :: "r"(s + 1) : "memory");

    // ---- stage 3: packed-f32x2 compute, one h per thread ----
    float* out0 = out + (size_t)b0 * ROW;
    float* out1 = out0 + ROW;     // batch b0+1

    // per-entity: property embedding AND rel-weight projection q_e = e . w_rel[0:4]
    u64 qd[NE];
    const ulonglong2* e4 = (const ulonglong2*)sh_ents[s];
    #pragma unroll
    for (int e = 0; e < NE; e++) {
        ulonglong2 q0 = e4[e*2 + 0];   // d0, d1 (each packed over 2 batches)
        ulonglong2 q1 = e4[e*2 + 1];   // d2, d3
        // prop: relu(e . w_prop + b_prop)
        u64 acc = fma2(q0.x, wp2[0], bp2);
        acc = fma2(q0.y, wp2[1], acc);
        acc = fma2(q1.x, wp2[2], acc);
        acc = fma2(q1.y, wp2[3], acc);
        float lo, hi; unpack2(acc, lo, hi);
        out0[e * OUTC + h] = fmaxf(lo, 0.f);
        out1[e * OUTC + h] = fmaxf(hi, 0.f);
        // q_e = e . w_rel[0:4]  (antisymmetric projection, shared by all pairs)
        u64 q = mul2(q0.x, wr2[0]);
        q = fma2(q0.y, wr2[1], q);
        q = fma2(q1.x, wr2[2], q);
        q = fma2(q1.y, wr2[3], q);
        qd[e] = q;
    }

    // relation embedding: sum_{j != i} relu((q_i - q_j) + dist*w4 + b)
    u64 racc[NE];
    #pragma unroll
    for (int e = 0; e < NE; e++) racc[e] = 0ULL;

    #pragma unroll
    for (int p = 0; p < NPAIR; p++) {
        const int i = PI[p], j = PJ[p];
        u64 sb = fma2(sh_dist[s][p], wr2[4], br2);   // symmetric part
        u64 sd = fma2(qd[j], neg1, qd[i]);           // q_i - q_j
        racc[i] = add2(racc[i], relu2(add2(sb, sd)));        // relu(sb + sd)
        racc[j] = add2(racc[j], relu2(fma2(sd, neg1, sb)));  // relu(sb - sd)
    }

    #pragma unroll
    for (int e = 0; e < NE; e++) {
        float lo, hi; unpack2(racc[e], lo, hi);
        out0[e * OUTC + H + h] = lo;
        out1[e * OUTC + H + h] = hi;
    }
}

extern "C" void kernel_launch(void* const* d_in, const int* in_sizes, int n_in,
                              void* d_out, int out_size) {
    const float* ctx    = (const float*)d_in[0];
    const float* w_prop = (const float*)d_in[1];
    const float* b_prop = (const float*)d_in[2];
    const float* w_rel  = (const float*)d_in[3];
    const float* b_rel  = (const float*)d_in[4];
    float* out = (float*)d_out;

    const int B = in_sizes[0] / (NE * DE);   // 16384
    enc_kernel<<<B / 4, 256>>>(ctx, w_prop, b_prop, w_rel, b_rel, out, B);
}